// round 1
// baseline (speedup 1.0000x reference)
#include <cuda_runtime.h>
#include <math_constants.h>

// HierarchicalSoftmax: x [B, 520] fp32.
// Segments per row: cols [0,8) = heads softmax; cols [8+64g, 8+64(g+1)) for
// g=0..7 = children softmaxes. All segment boundaries are float4-aligned:
//   heads   -> float4 indices [0, 2)
//   group g -> float4 indices [2+16g, 2+16g+16)
// A pair of adjacent children groups (2j, 2j+1) is 32 contiguous float4s
// (512B), so one warp-wide LDG.128 is fully coalesced and each 16-lane
// half-warp owns exactly one segment. Segmented reductions are then just
// butterfly shuffles with offsets 8,4,2,1 (stay inside each half-warp).
// One warp per row; no shared memory, no block sync.

#define NCOLS 520
#define NF4   130   // 520/4

__global__ __launch_bounds__(256) void hsoftmax_kernel(
    const float* __restrict__ x,
    float* __restrict__ out,
    int nrows)
{
    const unsigned FULL = 0xffffffffu;
    int warp = (blockIdx.x * blockDim.x + threadIdx.x) >> 5;
    int lane = threadIdx.x & 31;
    if (warp >= nrows) return;

    const float*  xrow = x   + (size_t)warp * NCOLS;
    float*        orow = out + (size_t)warp * NCOLS;
    const float4* x4   = reinterpret_cast<const float4*>(xrow);
    float4*       o4   = reinterpret_cast<float4*>(orow);

    // ---- Issue all loads up front (MLP=5) ----
    // Heads: lanes 0..7 load one scalar each (single 32B sector).
    float hv = (lane < 8) ? xrow[lane] : -CUDART_INF_F;

    // Children pairs j=0..3: warp-wide coalesced 512B load each.
    // float4 index for (j, lane) = 2 + 32*j + lane; half = lane>>4 selects
    // group g = 2j + half.
    float4 v0 = x4[2 + 32 * 0 + lane];
    float4 v1 = x4[2 + 32 * 1 + lane];
    float4 v2 = x4[2 + 32 * 2 + lane];
    float4 v3 = x4[2 + 32 * 3 + lane];

    // ---- Heads softmax (width-8 butterfly over lanes 0..7) ----
    {
        float m = hv;
        m = fmaxf(m, __shfl_xor_sync(FULL, m, 4));
        m = fmaxf(m, __shfl_xor_sync(FULL, m, 2));
        m = fmaxf(m, __shfl_xor_sync(FULL, m, 1));
        float e = __expf(hv - m);
        float s = e;
        s += __shfl_xor_sync(FULL, s, 4);
        s += __shfl_xor_sync(FULL, s, 2);
        s += __shfl_xor_sync(FULL, s, 1);
        if (lane < 8) orow[lane] = e / s;
    }

    // ---- Children: each 16-lane half owns one 64-elem group ----
    float4 vv[4] = {v0, v1, v2, v3};
#pragma unroll
    for (int j = 0; j < 4; ++j) {
        float4 v = vv[j];
        float m = fmaxf(fmaxf(v.x, v.y), fmaxf(v.z, v.w));
        m = fmaxf(m, __shfl_xor_sync(FULL, m, 8));
        m = fmaxf(m, __shfl_xor_sync(FULL, m, 4));
        m = fmaxf(m, __shfl_xor_sync(FULL, m, 2));
        m = fmaxf(m, __shfl_xor_sync(FULL, m, 1));
        float ex = __expf(v.x - m);
        float ey = __expf(v.y - m);
        float ez = __expf(v.z - m);
        float ew = __expf(v.w - m);
        float s = (ex + ey) + (ez + ew);
        s += __shfl_xor_sync(FULL, s, 8);
        s += __shfl_xor_sync(FULL, s, 4);
        s += __shfl_xor_sync(FULL, s, 2);
        s += __shfl_xor_sync(FULL, s, 1);
        float r = __frcp_rn(s);
        float4 o;
        o.x = ex * r; o.y = ey * r; o.z = ez * r; o.w = ew * r;
        o4[2 + 32 * j + lane] = o;   // coalesced 512B store
    }
}

extern "C" void kernel_launch(void* const* d_in, const int* in_sizes, int n_in,
                              void* d_out, int out_size)
{
    const float* x = (const float*)d_in[0];
    // d_in[1] (seg) is a compile-time-known structure; unused.
    float* out = (float*)d_out;

    int nrows = in_sizes[0] / NCOLS;   // 65536
    int warps_per_block = 8;           // 256 threads
    int blocks = (nrows + warps_per_block - 1) / warps_per_block;
    hsoftmax_kernel<<<blocks, warps_per_block * 32>>>(x, out, nrows);
}